// round 16
// baseline (speedup 1.0000x reference)
#include <cuda_runtime.h>
#include <cuda_bf16.h>
#include <math.h>

// ---------------- problem constants ----------------
#define BATCH   4
#define NSEQ    512
#define NDIM    1024
#define EDIM    64
#define HEADS   16
#define DOTD    64
#define FFN_H   2048
#define FFN_E   128
#define BN      (BATCH*NSEQ)
#define NN      (NSEQ*NSEQ)
#define BHN     (BATCH*HEADS)
#define EROWS   ((size_t)BATCH*NSEQ*NSEQ)
#define H_OUT_ELEMS (BN*NDIM)

// fast transcendental helpers
__device__ __forceinline__ float fast_elu(float x) {
    return x > 0.f ? x : (__expf(x) - 1.0f);
}
__device__ __forceinline__ float fast_sigmoid(float x) {
    return 1.0f / (1.0f + __expf(-x));
}

// ---------------- scratch ----------------
__device__ float g_hln [BN*NDIM];
__device__ float g_qkv [BN*3*NDIM];   // permuted: [row][h*192 + (q|k|v)*64 + d]
__device__ float g_E   [(size_t)BHN*NN];
__device__ float g_gate[(size_t)BHN*NN];
__device__ float g_H   [(size_t)BHN*NN];
__device__ float g_vatt[BN*NDIM];
__device__ float g_h1  [BN*NDIM];
__device__ float g_h2  [BN*NDIM];
__device__ float g_act [BN*FFN_H];

// ---------------- LayerNorm over 1024 ----------------
__global__ void __launch_bounds__(256) ln1024_kernel(
    const float* __restrict__ x, const float* __restrict__ g,
    const float* __restrict__ b, float* __restrict__ y)
{
    int row = blockIdx.x, t = threadIdx.x;
    const float* xr = x + (size_t)row * NDIM;
    float v[4]; float s = 0.f;
#pragma unroll
    for (int i = 0; i < 4; i++) { v[i] = xr[t + i*256]; s += v[i]; }
    __shared__ float red[8];
    int lane = t & 31, w = t >> 5;
#pragma unroll
    for (int o = 16; o; o >>= 1) s += __shfl_xor_sync(0xffffffff, s, o);
    if (lane == 0) red[w] = s;
    __syncthreads();
    float tot = 0.f;
#pragma unroll
    for (int i = 0; i < 8; i++) tot += red[i];
    float mu = tot * (1.0f/NDIM);
    __syncthreads();
    float q = 0.f;
#pragma unroll
    for (int i = 0; i < 4; i++) { float d = v[i]-mu; q += d*d; }
#pragma unroll
    for (int o = 16; o; o >>= 1) q += __shfl_xor_sync(0xffffffff, q, o);
    if (lane == 0) red[w] = q;
    __syncthreads();
    float qt = 0.f;
#pragma unroll
    for (int i = 0; i < 8; i++) qt += red[i];
    float rs = rsqrtf(qt * (1.0f/NDIM) + 1e-5f);
    float* yr = y + (size_t)row * NDIM;
#pragma unroll
    for (int i = 0; i < 4; i++) {
        int c = t + i*256;
        yr[c] = (v[i]-mu)*rs*g[c] + b[c];
    }
}

// ---------------- tf32 helpers ----------------
__device__ __forceinline__ float f2tf(float x) {
    unsigned r;
    asm("cvt.rna.tf32.f32 %0, %1;" : "=r"(r) : "f"(x));
    return __uint_as_float(r);
}

__device__ __forceinline__ void mma_tf32(float* c, const unsigned* a, const unsigned* b) {
    asm volatile(
        "mma.sync.aligned.m16n8k8.row.col.f32.tf32.tf32.f32 "
        "{%0,%1,%2,%3}, {%4,%5,%6,%7}, {%8,%9}, {%0,%1,%2,%3};\n"
        : "+f"(c[0]), "+f"(c[1]), "+f"(c[2]), "+f"(c[3])
        : "r"(a[0]), "r"(a[1]), "r"(a[2]), "r"(a[3]), "r"(b[0]), "r"(b[1]));
}

// ---------------- tf32 tensor-core GEMM (optional head-major output permute) --
#define AS_LD 17
#define BS_LD 132
__global__ void __launch_bounds__(256) gemm_tc_kernel(
    const float* __restrict__ A, const float* __restrict__ W,
    const float* __restrict__ bias, const float* __restrict__ res,
    float* __restrict__ C, int M, int N, int K, int act, int permute)
{
    __shared__ float As[2][128*AS_LD];
    __shared__ float Bs[2][16*BS_LD];

    int t = threadIdx.x;
    int lane = t & 31;
    int w = t >> 5;
    int wm = w & 3;
    int wn = w >> 2;
    int qr = lane >> 2;
    int qc = lane & 3;
    int n0 = blockIdx.x * 128, m0 = blockIdx.y * 128;

    int arow = t >> 1;
    int acol = (t & 1) * 8;
    int brow = t >> 4;
    int bcol = (t & 15) * 8;

    const float* Aptr = A + (size_t)(m0 + arow)*K + acol;
    const float* Bptr = W + (size_t)brow*N + n0 + bcol;

    float acc[2][8][4];
#pragma unroll
    for (int i = 0; i < 2; i++)
#pragma unroll
        for (int j = 0; j < 8; j++)
#pragma unroll
            for (int k = 0; k < 4; k++) acc[i][j][k] = 0.f;

    int KT = K / 16;
    float4 ra0, ra1, rb0, rb1;
    ra0 = *(const float4*)(Aptr + 0);
    ra1 = *(const float4*)(Aptr + 4);
    rb0 = *(const float4*)(Bptr + 0);
    rb1 = *(const float4*)(Bptr + 4);
    {
        float* as = As[0]; float* bs = Bs[0];
        int sa = arow*AS_LD + acol;
        as[sa+0]=f2tf(ra0.x); as[sa+1]=f2tf(ra0.y); as[sa+2]=f2tf(ra0.z); as[sa+3]=f2tf(ra0.w);
        as[sa+4]=f2tf(ra1.x); as[sa+5]=f2tf(ra1.y); as[sa+6]=f2tf(ra1.z); as[sa+7]=f2tf(ra1.w);
        int sb = brow*BS_LD + bcol;
        bs[sb+0]=f2tf(rb0.x); bs[sb+1]=f2tf(rb0.y); bs[sb+2]=f2tf(rb0.z); bs[sb+3]=f2tf(rb0.w);
        bs[sb+4]=f2tf(rb1.x); bs[sb+5]=f2tf(rb1.y); bs[sb+6]=f2tf(rb1.z); bs[sb+7]=f2tf(rb1.w);
    }
    __syncthreads();

    for (int kt = 0; kt < KT; kt++) {
        int cur = kt & 1;
        if (kt + 1 < KT) {
            int k0 = (kt + 1) * 16;
            ra0 = *(const float4*)(Aptr + k0);
            ra1 = *(const float4*)(Aptr + k0 + 4);
            rb0 = *(const float4*)(Bptr + (size_t)k0*N);
            rb1 = *(const float4*)(Bptr + (size_t)k0*N + 4);
        }
        const float* as = As[cur];
        const float* bs = Bs[cur];
#pragma unroll
        for (int ks = 0; ks < 2; ks++) {
            int k = ks * 8;
            unsigned af[2][4];
#pragma unroll
            for (int mt = 0; mt < 2; mt++) {
                int r0 = (wm*32 + mt*16 + qr) * AS_LD + k + qc;
                af[mt][0] = __float_as_uint(as[r0]);
                af[mt][1] = __float_as_uint(as[r0 + 8*AS_LD]);
                af[mt][2] = __float_as_uint(as[r0 + 4]);
                af[mt][3] = __float_as_uint(as[r0 + 8*AS_LD + 4]);
            }
            unsigned bf[8][2];
#pragma unroll
            for (int nt = 0; nt < 8; nt++) {
                int c0 = (k + qc)*BS_LD + wn*64 + nt*8 + qr;
                bf[nt][0] = __float_as_uint(bs[c0]);
                bf[nt][1] = __float_as_uint(bs[c0 + 4*BS_LD]);
            }
#pragma unroll
            for (int mt = 0; mt < 2; mt++)
#pragma unroll
                for (int nt = 0; nt < 8; nt++)
                    mma_tf32(acc[mt][nt], af[mt], bf[nt]);
        }
        if (kt + 1 < KT) {
            float* asw = As[cur ^ 1]; float* bsw = Bs[cur ^ 1];
            int sa = arow*AS_LD + acol;
            asw[sa+0]=f2tf(ra0.x); asw[sa+1]=f2tf(ra0.y); asw[sa+2]=f2tf(ra0.z); asw[sa+3]=f2tf(ra0.w);
            asw[sa+4]=f2tf(ra1.x); asw[sa+5]=f2tf(ra1.y); asw[sa+6]=f2tf(ra1.z); asw[sa+7]=f2tf(ra1.w);
            int sb = brow*BS_LD + bcol;
            bsw[sb+0]=f2tf(rb0.x); bsw[sb+1]=f2tf(rb0.y); bsw[sb+2]=f2tf(rb0.z); bsw[sb+3]=f2tf(rb0.w);
            bsw[sb+4]=f2tf(rb1.x); bsw[sb+5]=f2tf(rb1.y); bsw[sb+6]=f2tf(rb1.z); bsw[sb+7]=f2tf(rb1.w);
        }
        __syncthreads();
    }

#pragma unroll
    for (int mt = 0; mt < 2; mt++) {
        int mA = m0 + wm*32 + mt*16 + qr;
        int mB = mA + 8;
#pragma unroll
        for (int nt = 0; nt < 8; nt++) {
            int n = n0 + wn*64 + nt*8 + qc*2;
            float b0 = bias[n], b1 = bias[n + 1];
            float v0 = acc[mt][nt][0] + b0;
            float v1 = acc[mt][nt][1] + b1;
            float v2 = acc[mt][nt][2] + b0;
            float v3 = acc[mt][nt][3] + b1;
            if (act) {
                v0 = fast_elu(v0);
                v1 = fast_elu(v1);
                v2 = fast_elu(v2);
                v3 = fast_elu(v3);
            }
            if (res) {
                const float* rA = res + (size_t)mA*N + n;
                const float* rB = res + (size_t)mB*N + n;
                v0 += rA[0]; v1 += rA[1];
                v2 += rB[0]; v3 += rB[1];
            }
            if (permute) {
                int pn0 = (n & 15)*192 + (n >> 4);
                int pn1 = ((n+1) & 15)*192 + ((n+1) >> 4);
                C[(size_t)mA*N + pn0] = v0;
                C[(size_t)mA*N + pn1] = v1;
                C[(size_t)mB*N + pn0] = v2;
                C[(size_t)mB*N + pn1] = v3;
            } else {
                float2 oA; oA.x = v0; oA.y = v1;
                float2 oB; oB.x = v2; oB.y = v3;
                *(float2*)(C + (size_t)mA*N + n) = oA;
                *(float2*)(C + (size_t)mB*N + n) = oB;
            }
        }
    }
}

// ---------------- e -> LN(shfl-fused) -> [E|G] projection via tf32 mma -------
__global__ void __launch_bounds__(256) eg_kernel(
    const float* __restrict__ e,
    const float* __restrict__ lng, const float* __restrict__ lnb,
    const float* __restrict__ WE, const float* __restrict__ bE,
    const float* __restrict__ WG, const float* __restrict__ bG)
{
    __shared__ float xs[64*68];
    __shared__ float Wc[64*36];
    __shared__ float ob[32*65];
    __shared__ float sg[64], sb[64], sbc[32];
    int t = threadIdx.x;
    size_t row0 = (size_t)blockIdx.x * 64;

    for (int i = t; i < 1024; i += 256) {
        int k = i >> 4, o = i & 15;
        Wc[k*36 + o]      = f2tf(WE[i]);
        Wc[k*36 + 16 + o] = f2tf(WG[i]);
    }
    if (t < 64) { sg[t] = lng[t]; sb[t] = lnb[t]; }
    if (t >= 64 && t < 80)  sbc[t - 64] = bE[t - 64];
    if (t >= 80 && t < 96)  sbc[t - 64] = bG[t - 80];
    __syncthreads();

#pragma unroll
    for (int i = 0; i < 4; i++) {
        int idx4 = t + i*256;
        int r = idx4 >> 4, c4 = idx4 & 15;
        float4 v = *(const float4*)&e[row0*64 + (size_t)r*64 + c4*4];
        float ps = v.x + v.y + v.z + v.w;
        float pq = v.x*v.x + v.y*v.y + v.z*v.z + v.w*v.w;
        ps += __shfl_xor_sync(0xffffffff, ps, 1);
        ps += __shfl_xor_sync(0xffffffff, ps, 2);
        ps += __shfl_xor_sync(0xffffffff, ps, 4);
        ps += __shfl_xor_sync(0xffffffff, ps, 8);
        pq += __shfl_xor_sync(0xffffffff, pq, 1);
        pq += __shfl_xor_sync(0xffffffff, pq, 2);
        pq += __shfl_xor_sync(0xffffffff, pq, 4);
        pq += __shfl_xor_sync(0xffffffff, pq, 8);
        float mu = ps * (1.0f/64.0f);
        float rs = rsqrtf(pq * (1.0f/64.0f) - mu*mu + 1e-5f);
        int c = c4*4;
        xs[r*68 + c + 0] = f2tf((v.x - mu)*rs*sg[c+0] + sb[c+0]);
        xs[r*68 + c + 1] = f2tf((v.y - mu)*rs*sg[c+1] + sb[c+1]);
        xs[r*68 + c + 2] = f2tf((v.z - mu)*rs*sg[c+2] + sb[c+2]);
        xs[r*68 + c + 3] = f2tf((v.w - mu)*rs*sg[c+3] + sb[c+3]);
    }
    __syncthreads();

    int lane = t & 31;
    int w = t >> 5;
    int wm = w & 3;
    int wn = w >> 2;
    int qr = lane >> 2, qc = lane & 3;
    {
        float acc[2][4];
#pragma unroll
        for (int j = 0; j < 2; j++)
#pragma unroll
            for (int k = 0; k < 4; k++) acc[j][k] = 0.f;
#pragma unroll
        for (int k8 = 0; k8 < 8; k8++) {
            int k = k8 * 8;
            unsigned af[4];
            int r0 = (wm*16 + qr)*68 + k + qc;
            af[0] = __float_as_uint(xs[r0]);
            af[1] = __float_as_uint(xs[r0 + 8*68]);
            af[2] = __float_as_uint(xs[r0 + 4]);
            af[3] = __float_as_uint(xs[r0 + 8*68 + 4]);
#pragma unroll
            for (int nt = 0; nt < 2; nt++) {
                int c0 = (k + qc)*36 + wn*16 + nt*8 + qr;
                unsigned bf[2];
                bf[0] = __float_as_uint(Wc[c0]);
                bf[1] = __float_as_uint(Wc[c0 + 4*36]);
                mma_tf32(acc[nt], af, bf);
            }
        }
#pragma unroll
        for (int nt = 0; nt < 2; nt++) {
            int o = wn*16 + nt*8 + qc*2;
            int lA = wm*16 + qr, lB = lA + 8;
            float v0 = acc[nt][0] + sbc[o];
            float v1 = acc[nt][1] + sbc[o+1];
            float v2 = acc[nt][2] + sbc[o];
            float v3 = acc[nt][3] + sbc[o+1];
            if (o >= 16) {
                v0 = fast_sigmoid(v0);
                v1 = fast_sigmoid(v1);
                v2 = fast_sigmoid(v2);
                v3 = fast_sigmoid(v3);
            }
            ob[o*65 + lA]     = v0;
            ob[(o+1)*65 + lA] = v1;
            ob[o*65 + lB]     = v2;
            ob[(o+1)*65 + lB] = v3;
        }
    }
    __syncthreads();

    int b_ = (int)(row0 >> 18);
    int rem = (int)(row0 & (NN - 1));
    int l = rem >> 9, m0 = rem & 511;
#pragma unroll
    for (int i = 0; i < 8; i++) {
        int idx = t + i*256;
        int o = idx >> 6, rr = idx & 63;
        float val = ob[o*65 + rr];
        int hd = o & 15;
        size_t dst = ((size_t)(b_*HEADS + hd))*NN + (size_t)l*512 + m0 + rr;
        if (o < 16) g_E[dst] = val; else g_gate[dst] = val;
    }
}

// ---------------- fused attention v10 (tf32 mma, 512 threads, 2 blocks/SM) ---
#define AV3_HLD  37
#define AV3_HS   0
#define AV3_QS   18944
#define AV3_KVS  21120
#define AV3_SMEM 25504
__global__ void __launch_bounds__(512) av2_kernel(const float* __restrict__ qkv)
{
    extern __shared__ float sm[];
    float* Hs  = sm + AV3_HS;
    float* Qs  = sm + AV3_QS;
    float* KVs = sm + AV3_KVS;

    int t = threadIdx.x;
    int l0 = blockIdx.x * 32;
    int z = blockIdx.y;
    int b = z >> 4, hd = z & 15;
    int lane = t & 31;
    int w = t >> 5;               // 0..15
    int wm = w & 1;               // l-tile of 16
    int wn = w >> 1;              // m/n chunk of 8 (0..7)
    int qr = lane >> 2, qc = lane & 3;
    size_t zbase = (size_t)z * NN;
    const float* qb = qkv + (size_t)b*NSEQ*3*NDIM + hd*192;

    // load Q strip [l][d] coalesced (512 float4s, 1 per thread)
    {
        int lloc = t >> 4, d4 = t & 15;
        float4 v = *(const float4*)&qb[(size_t)(l0 + lloc)*(3*NDIM) + d4*4];
        v.x = f2tf(v.x); v.y = f2tf(v.y); v.z = f2tf(v.z); v.w = f2tf(v.w);
        *(float4*)&Qs[lloc*68 + d4*4] = v;
    }

    // Phase 1 with K-tile register prefetch
    float4 pk[2];
#pragma unroll
    for (int i = 0; i < 2; i++) {
        int idx4 = t + i*512;
        int mloc = idx4 >> 4, d4 = idx4 & 15;
        pk[i] = *(const float4*)&qb[(size_t)mloc*(3*NDIM) + 64 + d4*4];
    }
    for (int mt = 0; mt < 8; mt++) {
        int m0g = mt * 64;
#pragma unroll
        for (int i = 0; i < 2; i++) {
            int idx4 = t + i*512;
            int mloc = idx4 >> 4, d4 = idx4 & 15;
            KVs[(d4*4+0)*68 + mloc] = f2tf(pk[i].x);
            KVs[(d4*4+1)*68 + mloc] = f2tf(pk[i].y);
            KVs[(d4*4+2)*68 + mloc] = f2tf(pk[i].z);
            KVs[(d4*4+3)*68 + mloc] = f2tf(pk[i].w);
        }
        __syncthreads();
        if (mt < 7) {
            int m1 = (mt + 1) * 64;
#pragma unroll
            for (int i = 0; i < 2; i++) {
                int idx4 = t + i*512;
                int mloc = idx4 >> 4, d4 = idx4 & 15;
                pk[i] = *(const float4*)&qb[(size_t)(m1 + mloc)*(3*NDIM) + 64 + d4*4];
            }
        }

        float acc[4];
#pragma unroll
        for (int k = 0; k < 4; k++) acc[k] = 0.f;
#pragma unroll
        for (int k8 = 0; k8 < 8; k8++) {
            int k = k8 * 8;
            unsigned af[4];
            int r0 = (wm*16 + qr)*68 + k + qc;
            af[0] = __float_as_uint(Qs[r0]);
            af[1] = __float_as_uint(Qs[r0 + 8*68]);
            af[2] = __float_as_uint(Qs[r0 + 4]);
            af[3] = __float_as_uint(Qs[r0 + 8*68 + 4]);
            int c0 = (k + qc)*68 + wn*8 + qr;
            unsigned bf[2];
            bf[0] = __float_as_uint(KVs[c0]);
            bf[1] = __float_as_uint(KVs[c0 + 4*68]);
            mma_tf32(acc, af, bf);
        }
        {
            int mg = m0g + wn*8 + qc*2;
            int lA = wm*16 + qr, lB = lA + 8;
            Hs[(mg+0)*AV3_HLD + lA] = acc[0];
            Hs[(mg+1)*AV3_HLD + lA] = acc[1];
            Hs[(mg+0)*AV3_HLD + lB] = acc[2];
            Hs[(mg+1)*AV3_HLD + lB] = acc[3];
        }
        __syncthreads();
    }

    // scale, clip, +E -> g_H and Hs (coalesced, 32 iters)
    for (int ii = 0; ii < 32; ii++) {
        int idx = ii*512 + t;
        int l = idx >> 9, m = idx & 511;
        size_t ro = zbase + (size_t)(l0 + l)*512 + m;
        float v = fminf(fmaxf(Hs[m*AV3_HLD + l]*0.125f, -5.f), 5.f) + g_E[ro];
        g_H[ro] = v;
        Hs[m*AV3_HLD + l] = v;
    }
    __syncthreads();

    // fused softmax + gate + inv (16 threads/row)
    {
        int r = t >> 4, part = t & 15;
        const float* gr = g_gate + zbase + (size_t)(l0 + r)*512;
        float mx = -1e30f;
        for (int i = 0; i < 32; i++) {
            int m = i*16 + part;
            mx = fmaxf(mx, Hs[m*AV3_HLD + r]);
        }
        mx = fmaxf(mx, __shfl_xor_sync(0xffffffff, mx, 1));
        mx = fmaxf(mx, __shfl_xor_sync(0xffffffff, mx, 2));
        mx = fmaxf(mx, __shfl_xor_sync(0xffffffff, mx, 4));
        mx = fmaxf(mx, __shfl_xor_sync(0xffffffff, mx, 8));
        float s = 0.f;
        for (int i = 0; i < 32; i++) {
            int m = i*16 + part;
            float ve = __expf(Hs[m*AV3_HLD + r] - mx);
            s += ve;
            Hs[m*AV3_HLD + r] = ve * gr[m];
        }
        s += __shfl_xor_sync(0xffffffff, s, 1);
        s += __shfl_xor_sync(0xffffffff, s, 2);
        s += __shfl_xor_sync(0xffffffff, s, 4);
        s += __shfl_xor_sync(0xffffffff, s, 8);
        float inv = 1.0f / s;
        for (int i = 0; i < 32; i++) {
            int m = i*16 + part;
            Hs[m*AV3_HLD + r] = f2tf(Hs[m*AV3_HLD + r] * inv);
        }
    }
    __syncthreads();

    // Phase 4: A@V with V-tile register prefetch
    float acc2[4];
#pragma unroll
    for (int k = 0; k < 4; k++) acc2[k] = 0.f;
    float4 pv[2];
#pragma unroll
    for (int i = 0; i < 2; i++) {
        int idx4 = t + i*512;
        int mloc = idx4 >> 4, k4 = idx4 & 15;
        pv[i] = *(const float4*)&qb[(size_t)mloc*(3*NDIM) + 128 + k4*4];
    }
    for (int mt = 0; mt < 8; mt++) {
        int m0g = mt * 64;
#pragma unroll
        for (int i = 0; i < 2; i++) {
            int idx4 = t + i*512;
            int mloc = idx4 >> 4, k4 = idx4 & 15;
            float4 v = pv[i];
            v.x = f2tf(v.x); v.y = f2tf(v.y); v.z = f2tf(v.z); v.w = f2tf(v.w);
            *(float4*)&KVs[mloc*68 + k4*4] = v;
        }
        __syncthreads();
        if (mt < 7) {
            int m1 = (mt + 1) * 64;
#pragma unroll
            for (int i = 0; i < 2; i++) {
                int idx4 = t + i*512;
                int mloc = idx4 >> 4, k4 = idx4 & 15;
                pv[i] = *(const float4*)&qb[(size_t)(m1 + mloc)*(3*NDIM) + 128 + k4*4];
            }
        }
#pragma unroll
        for (int k8 = 0; k8 < 8; k8++) {
            int kk = k8 * 8;
            unsigned af[4];
            int a0 = (m0g + kk + qc)*AV3_HLD + wm*16 + qr;
            af[0] = __float_as_uint(Hs[a0]);
            af[1] = __float_as_uint(Hs[a0 + 8]);
            af[2] = __float_as_uint(Hs[a0 + 4*AV3_HLD]);
            af[3] = __float_as_uint(Hs[a0 + 4*AV3_HLD + 8]);
            int c0 = (kk + qc)*68 + wn*8 + qr;
            unsigned bf[2];
            bf[0] = __float_as_uint(KVs[c0]);
            bf[1] = __float_as_uint(KVs[c0 + 4*68]);
            mma_tf32(acc2, af, bf);
        }
        __syncthreads();
    }
    {
        int lA = l0 + wm*16 + qr;
        int lB = lA + 8;
        int kout = wn*8 + qc*2;
        g_vatt[(size_t)(b*NSEQ + lA)*NDIM + (kout+0)*16 + hd] = acc2[0];
        g_vatt[(size_t)(b*NSEQ + lA)*NDIM + (kout+1)*16 + hd] = acc2[1];
        g_vatt[(size_t)(b*NSEQ + lB)*NDIM + (kout+0)*16 + hd] = acc2[2];
        g_vatt[(size_t)(b*NSEQ + lB)*NDIM + (kout+1)*16 + hd] = acc2[3];
    }
}

// ---------------- persistent fused e-out v6: 512 threads, 2 blocks/SM -------
#define EO_W1   0
#define EO_W2   8448
#define EO_WOE  17152
#define EO_HG   18176
#define EO_XS   18752
#define EO_XSN  20832
#define EO_HS   23008
#define EO_PAR  27232
#define EO_SMEM_FLOATS 27680
__global__ void __launch_bounds__(512) eout_kernel(
    const float* __restrict__ e,
    const float* __restrict__ WOe, const float* __restrict__ bOe,
    const float* __restrict__ lng, const float* __restrict__ lnb,
    const float* __restrict__ W1, const float* __restrict__ b1,
    const float* __restrict__ W2, const float* __restrict__ b2,
    float* __restrict__ eout)
{
    extern __shared__ float sm[];
    float* W1s  = sm + EO_W1;
    float* W2s  = sm + EO_W2;
    float* WOes = sm + EO_WOE;
    float* Hg   = sm + EO_HG;
    float* xs   = sm + EO_XS;
    float* xsn  = sm + EO_XSN;
    float* hs   = sm + EO_HS;
    float* sbOe = sm + EO_PAR;
    float* sge  = sbOe + 64;
    float* sbe  = sge  + 64;
    float* sb1  = sbe  + 64;
    float* sb2  = sb1  + 128;

    int t = threadIdx.x;
    int bid = blockIdx.x;
    int b_ = bid >> 9;
    int l  = bid & 511;
    const float* Hbase = g_H + (size_t)(b_*HEADS)*NN + (size_t)l*512;

    for (int i = t; i < 8192; i += 512) {
        W1s[(i >> 7)*132 + (i & 127)] = f2tf(W1[i]);
        W2s[(i >> 6)*68  + (i & 63)]  = f2tf(W2[i]);
    }
    for (int i = t; i < 1024; i += 512) WOes[i] = WOe[i];
    if (t < 64) { sbOe[t] = bOe[t]; sge[t] = lng[t]; sbe[t] = lnb[t]; sb2[t] = b2[t]; }
    if (t >= 64 && t < 192) sb1[t - 64] = b1[t - 64];

    int lane = t & 31;
    int w = t >> 5;               // 0..15
    int wm = w & 1;
    int wn = w >> 1;              // 0..7
    int qr = lane >> 2, qc = lane & 3;
    int tx = t & 15, ty = t >> 4; // ty 0..31 (one row per thread)

    // prefetch group 0
    float hgp;
    float4 ep;
    {
        int hd0 = t >> 5, m0_ = t & 31;
        hgp = Hbase[(size_t)hd0*NN + m0_];
        size_t row0 = (size_t)bid * 512;
        ep = *(const float4*)&e[(row0 + ty)*64 + tx*4];
    }
    __syncthreads();

    for (int g = 0; g < 16; g++) {
        int m0 = g * 32;
        size_t row0 = (size_t)bid * 512 + m0;

        // store prefetched Hg (512 values, 1 per thread)
        {
            int hd0 = t >> 5, m = t & 31;
            Hg[hd0*36 + m] = hgp;
        }
        __syncthreads();

        // Phase A (fused): x = Hg^T@WOe + bOe + e; LN via shfl; xsn = tf32(LN(x))
        {
            float acc[4];
#pragma unroll
            for (int j = 0; j < 4; j++) acc[j] = 0.f;
#pragma unroll
            for (int hd = 0; hd < 16; hd++) {
                float a = Hg[hd*36 + ty];
                float wv[4];
#pragma unroll
                for (int j = 0; j < 4; j++) wv[j] = WOes[hd*64 + tx*4 + j];
#pragma unroll
                for (int j = 0; j < 4; j++) acc[j] += a*wv[j];
            }
            int r = ty;
            float v0 = acc[0] + sbOe[tx*4+0] + ep.x;
            float v1 = acc[1] + sbOe[tx*4+1] + ep.y;
            float v2 = acc[2] + sbOe[tx*4+2] + ep.z;
            float v3 = acc[3] + sbOe[tx*4+3] + ep.w;
            xs[r*65 + tx*4 + 0] = v0;
            xs[r*65 + tx*4 + 1] = v1;
            xs[r*65 + tx*4 + 2] = v2;
            xs[r*65 + tx*4 + 3] = v3;
            float ps = v0 + v1 + v2 + v3;
            float pq = v0*v0 + v1*v1 + v2*v2 + v3*v3;
            ps += __shfl_xor_sync(0xffffffff, ps, 1);
            ps += __shfl_xor_sync(0xffffffff, ps, 2);
            ps += __shfl_xor_sync(0xffffffff, ps, 4);
            ps += __shfl_xor_sync(0xffffffff, ps, 8);
            pq += __shfl_xor_sync(0xffffffff, pq, 1);
            pq += __shfl_xor_sync(0xffffffff, pq, 2);
            pq += __shfl_xor_sync(0xffffffff, pq, 4);
            pq += __shfl_xor_sync(0xffffffff, pq, 8);
            float mu = ps * (1.0f/64.0f);
            float rs = rsqrtf(pq * (1.0f/64.0f) - mu*mu + 1e-5f);
            int c = tx*4;
            xsn[r*68 + c + 0] = f2tf((v0 - mu)*rs*sge[c+0] + sbe[c+0]);
            xsn[r*68 + c + 1] = f2tf((v1 - mu)*rs*sge[c+1] + sbe[c+1]);
            xsn[r*68 + c + 2] = f2tf((v2 - mu)*rs*sge[c+2] + sbe[c+2]);
            xsn[r*68 + c + 3] = f2tf((v3 - mu)*rs*sge[c+3] + sbe[c+3]);
        }
        __syncthreads();

        // prefetch next group's Hg + e (overlaps C/E mma phases)
        if (g < 15) {
            int m1 = (g + 1) * 32;
            int hd0 = t >> 5, mm = t & 31;
            hgp = Hbase[(size_t)hd0*NN + m1 + mm];
            size_t row1 = (size_t)bid * 512 + m1;
            ep = *(const float4*)&e[(row1 + ty)*64 + tx*4];
        }

        // Phase C (mma): hidden = elu( xsn @ W1 + b1 ), 16 warps, 2 n-tiles each
        {
            float acc[2][4];
#pragma unroll
            for (int j = 0; j < 2; j++)
#pragma unroll
                for (int k = 0; k < 4; k++) acc[j][k] = 0.f;
#pragma unroll
            for (int k8 = 0; k8 < 8; k8++) {
                int k = k8 * 8;
                unsigned af[4];
                int r0 = (wm*16 + qr)*68 + k + qc;
                af[0] = __float_as_uint(xsn[r0]);
                af[1] = __float_as_uint(xsn[r0 + 8*68]);
                af[2] = __float_as_uint(xsn[r0 + 4]);
                af[3] = __float_as_uint(xsn[r0 + 8*68 + 4]);
#pragma unroll
                for (int nt = 0; nt < 2; nt++) {
                    int c0 = (k + qc)*132 + wn*16 + nt*8 + qr;
                    unsigned bf[2];
                    bf[0] = __float_as_uint(W1s[c0]);
                    bf[1] = __float_as_uint(W1s[c0 + 4*132]);
                    mma_tf32(acc[nt], af, bf);
                }
            }
#pragma unroll
            for (int nt = 0; nt < 2; nt++) {
                int n = wn*16 + nt*8 + qc*2;
                int mA = wm*16 + qr, mB = mA + 8;
                float v0 = fast_elu(acc[nt][0] + sb1[n]);
                float v1 = fast_elu(acc[nt][1] + sb1[n+1]);
                float v2 = fast_elu(acc[nt][2] + sb1[n]);
                float v3 = fast_elu(acc[nt][3] + sb1[n+1]);
                hs[mA*132 + n]     = f2tf(v0);
                hs[mA*132 + n + 1] = f2tf(v1);
                hs[mB*132 + n]     = f2tf(v2);
                hs[mB*132 + n + 1] = f2tf(v3);
            }
        }
        __syncthreads();

        // Phase E (mma): out = hs @ W2 + b2 + xs, 16 warps, 1 n-tile each
        {
            float acc[4];
#pragma unroll
            for (int k = 0; k < 4; k++) acc[k] = 0.f;
#pragma unroll
            for (int k8 = 0; k8 < 16; k8++) {
                int k = k8 * 8;
                unsigned af[4];
                int r0 = (wm*16 + qr)*132 + k + qc;
                af[0] = __float_as_uint(hs[r0]);
                af[1] = __float_as_uint(hs[r0 + 8*132]);
                af[2] = __float_as_uint(hs[r0 + 4]);
                af[3] = __float_as_uint(hs[r0 + 8*132 + 4]);
                int c0 = (k + qc)*68 + wn*8 + qr;
                unsigned bf[2];
                bf[0] = __float_as_uint(W2s[c0]);
                bf[1] = __float_as_uint(W2s[c0 + 4*68]);
                mma_tf32(acc, af, bf);
            }
            {
                int n = wn*8 + qc*2;
                int mA = wm*16 + qr, mB = mA + 8;
                float2 oA, oB;
                oA.x = acc[0] + sb2[n]   + xs[mA*65 + n];
                oA.y = acc[1] + sb2[n+1] + xs[mA*65 + n + 1];
                oB.x = acc[2] + sb2[n]   + xs[mB*65 + n];
                oB.y = acc[3] + sb2[n+1] + xs[mB*65 + n + 1];
                *(float2*)&eout[(row0 + mA)*64 + n] = oA;
                *(float2*)&eout[(row0 + mB)*64 + n] = oB;
            }
        }
        __syncthreads();
    }
}

// ---------------- host launcher ----------------
extern "C" void kernel_launch(void* const* d_in, const int* in_sizes, int n_in,
                              void* d_out, int out_size)
{
    const float* h        = (const float*)d_in[0];
    const float* e        = (const float*)d_in[1];
    const float* ln_h_g   = (const float*)d_in[2];
    const float* ln_h_b   = (const float*)d_in[3];
    const float* ln_e_g   = (const float*)d_in[4];
    const float* ln_e_b   = (const float*)d_in[5];
    const float* W_E      = (const float*)d_in[6];
    const float* b_E      = (const float*)d_in[7];
    const float* W_QKV    = (const float*)d_in[8];
    const float* b_QKV    = (const float*)d_in[9];
    const float* W_G      = (const float*)d_in[10];
    const float* b_G      = (const float*)d_in[11];
    const float* W_Oh     = (const float*)d_in[12];
    const float* b_Oh     = (const float*)d_in[13];
    const float* ffn_ln_h_g = (const float*)d_in[14];
    const float* ffn_ln_h_b = (const float*)d_in[15];
    const float* W_h1     = (const float*)d_in[16];
    const float* b_h1     = (const float*)d_in[17];
    const float* W_h2     = (const float*)d_in[18];
    const float* b_h2     = (const float*)d_in[19];
    const float* W_Oe     = (const float*)d_in[20];
    const float* b_Oe     = (const float*)d_in[21];
    const float* ffn_ln_e_g = (const float*)d_in[22];
    const float* ffn_ln_e_b = (const float*)d_in[23];
    const float* W_e1     = (const float*)d_in[24];
    const float* b_e1     = (const float*)d_in[25];
    const float* W_e2     = (const float*)d_in[26];
    const float* b_e2     = (const float*)d_in[27];

    float* out_h = (float*)d_out;
    float* out_e = out_h + H_OUT_ELEMS;

    float *p_hln, *p_qkv, *p_vatt, *p_h1, *p_h2, *p_act;
    cudaGetSymbolAddress((void**)&p_hln,  g_hln);
    cudaGetSymbolAddress((void**)&p_qkv,  g_qkv);
    cudaGetSymbolAddress((void**)&p_vatt, g_vatt);
    cudaGetSymbolAddress((void**)&p_h1,   g_h1);
    cudaGetSymbolAddress((void**)&p_h2,   g_h2);
    cudaGetSymbolAddress((void**)&p_act,  g_act);

    // h path pre-attention (QKV gemm writes head-major permuted output)
    ln1024_kernel<<<BN, 256>>>(h, ln_h_g, ln_h_b, p_hln);
    gemm_tc_kernel<<<dim3(3*NDIM/128, BN/128), 256>>>(p_hln, W_QKV, b_QKV, nullptr, p_qkv,
                                                      BN, 3*NDIM, NDIM, 0, 1);
    // e path: LN + E/G projections (mma, fused LN)
    eg_kernel<<<(unsigned)(EROWS/64), 256>>>(e, ln_e_g, ln_e_b, W_E, b_E, W_G, b_G);
    // fused attention (tf32 mma, 512 threads, 2 blocks/SM)
    cudaFuncSetAttribute(av2_kernel, cudaFuncAttributeMaxDynamicSharedMemorySize,
                         AV3_SMEM * 4);
    av2_kernel<<<dim3(16, BHN), 512, AV3_SMEM * 4>>>(p_qkv);
    // h path post-attention
    gemm_tc_kernel<<<dim3(NDIM/128, BN/128), 256>>>(p_vatt, W_Oh, b_Oh, h, p_h1,
                                                    BN, NDIM, NDIM, 0, 0);
    ln1024_kernel<<<BN, 256>>>(p_h1, ffn_ln_h_g, ffn_ln_h_b, p_h2);
    gemm_tc_kernel<<<dim3(FFN_H/128, BN/128), 256>>>(p_h2, W_h1, b_h1, nullptr, p_act,
                                                     BN, FFN_H, NDIM, 1, 0);
    gemm_tc_kernel<<<dim3(NDIM/128, BN/128), 256>>>(p_act, W_h2, b_h2, p_h1, out_h,
                                                    BN, NDIM, FFN_H, 0, 0);
    // fused e output path (512 threads, 2 blocks/SM)
    cudaFuncSetAttribute(eout_kernel, cudaFuncAttributeMaxDynamicSharedMemorySize,
                         EO_SMEM_FLOATS * 4);
    eout_kernel<<<BN, 512, EO_SMEM_FLOATS * 4>>>(
        e, W_Oe, b_Oe, ffn_ln_e_g, ffn_ln_e_b, W_e1, b_e1, W_e2, b_e2, out_e);
}

// round 17
// speedup vs baseline: 1.0942x; 1.0942x over previous
#include <cuda_runtime.h>
#include <cuda_bf16.h>
#include <math.h>

// ---------------- problem constants ----------------
#define BATCH   4
#define NSEQ    512
#define NDIM    1024
#define EDIM    64
#define HEADS   16
#define DOTD    64
#define FFN_H   2048
#define FFN_E   128
#define BN      (BATCH*NSEQ)
#define NN      (NSEQ*NSEQ)
#define BHN     (BATCH*HEADS)
#define EROWS   ((size_t)BATCH*NSEQ*NSEQ)
#define H_OUT_ELEMS (BN*NDIM)

// fast transcendental helpers
__device__ __forceinline__ float fast_elu(float x) {
    return x > 0.f ? x : (__expf(x) - 1.0f);
}
__device__ __forceinline__ float fast_sigmoid(float x) {
    return 1.0f / (1.0f + __expf(-x));
}

// ---------------- scratch ----------------
__device__ float g_hln [BN*NDIM];
__device__ float g_qkv [BN*3*NDIM];   // permuted: [row][h*192 + (q|k|v)*64 + d]
__device__ float g_E   [(size_t)BHN*NN];
__device__ float g_gate[(size_t)BHN*NN];
__device__ float g_H   [(size_t)BHN*NN];
__device__ float g_vatt[BN*NDIM];
__device__ float g_h1  [BN*NDIM];
__device__ float g_h2  [BN*NDIM];
__device__ float g_act [BN*FFN_H];

// ---------------- LayerNorm over 1024 ----------------
__global__ void __launch_bounds__(256) ln1024_kernel(
    const float* __restrict__ x, const float* __restrict__ g,
    const float* __restrict__ b, float* __restrict__ y)
{
    int row = blockIdx.x, t = threadIdx.x;
    const float* xr = x + (size_t)row * NDIM;
    float v[4]; float s = 0.f;
#pragma unroll
    for (int i = 0; i < 4; i++) { v[i] = xr[t + i*256]; s += v[i]; }
    __shared__ float red[8];
    int lane = t & 31, w = t >> 5;
#pragma unroll
    for (int o = 16; o; o >>= 1) s += __shfl_xor_sync(0xffffffff, s, o);
    if (lane == 0) red[w] = s;
    __syncthreads();
    float tot = 0.f;
#pragma unroll
    for (int i = 0; i < 8; i++) tot += red[i];
    float mu = tot * (1.0f/NDIM);
    __syncthreads();
    float q = 0.f;
#pragma unroll
    for (int i = 0; i < 4; i++) { float d = v[i]-mu; q += d*d; }
#pragma unroll
    for (int o = 16; o; o >>= 1) q += __shfl_xor_sync(0xffffffff, q, o);
    if (lane == 0) red[w] = q;
    __syncthreads();
    float qt = 0.f;
#pragma unroll
    for (int i = 0; i < 8; i++) qt += red[i];
    float rs = rsqrtf(qt * (1.0f/NDIM) + 1e-5f);
    float* yr = y + (size_t)row * NDIM;
#pragma unroll
    for (int i = 0; i < 4; i++) {
        int c = t + i*256;
        yr[c] = (v[i]-mu)*rs*g[c] + b[c];
    }
}

// ---------------- tf32 helpers ----------------
__device__ __forceinline__ float f2tf(float x) {
    unsigned r;
    asm("cvt.rna.tf32.f32 %0, %1;" : "=r"(r) : "f"(x));
    return __uint_as_float(r);
}

__device__ __forceinline__ void mma_tf32(float* c, const unsigned* a, const unsigned* b) {
    asm volatile(
        "mma.sync.aligned.m16n8k8.row.col.f32.tf32.tf32.f32 "
        "{%0,%1,%2,%3}, {%4,%5,%6,%7}, {%8,%9}, {%0,%1,%2,%3};\n"
        : "+f"(c[0]), "+f"(c[1]), "+f"(c[2]), "+f"(c[3])
        : "r"(a[0]), "r"(a[1]), "r"(a[2]), "r"(a[3]), "r"(b[0]), "r"(b[1]));
}

// ---------------- tf32 tensor-core GEMM (optional head-major output permute) --
#define AS_LD 17
#define BS_LD 132
__global__ void __launch_bounds__(256) gemm_tc_kernel(
    const float* __restrict__ A, const float* __restrict__ W,
    const float* __restrict__ bias, const float* __restrict__ res,
    float* __restrict__ C, int M, int N, int K, int act, int permute)
{
    __shared__ float As[2][128*AS_LD];
    __shared__ float Bs[2][16*BS_LD];

    int t = threadIdx.x;
    int lane = t & 31;
    int w = t >> 5;
    int wm = w & 3;
    int wn = w >> 2;
    int qr = lane >> 2;
    int qc = lane & 3;
    int n0 = blockIdx.x * 128, m0 = blockIdx.y * 128;

    int arow = t >> 1;
    int acol = (t & 1) * 8;
    int brow = t >> 4;
    int bcol = (t & 15) * 8;

    const float* Aptr = A + (size_t)(m0 + arow)*K + acol;
    const float* Bptr = W + (size_t)brow*N + n0 + bcol;

    float acc[2][8][4];
#pragma unroll
    for (int i = 0; i < 2; i++)
#pragma unroll
        for (int j = 0; j < 8; j++)
#pragma unroll
            for (int k = 0; k < 4; k++) acc[i][j][k] = 0.f;

    int KT = K / 16;
    float4 ra0, ra1, rb0, rb1;
    ra0 = *(const float4*)(Aptr + 0);
    ra1 = *(const float4*)(Aptr + 4);
    rb0 = *(const float4*)(Bptr + 0);
    rb1 = *(const float4*)(Bptr + 4);
    {
        float* as = As[0]; float* bs = Bs[0];
        int sa = arow*AS_LD + acol;
        as[sa+0]=f2tf(ra0.x); as[sa+1]=f2tf(ra0.y); as[sa+2]=f2tf(ra0.z); as[sa+3]=f2tf(ra0.w);
        as[sa+4]=f2tf(ra1.x); as[sa+5]=f2tf(ra1.y); as[sa+6]=f2tf(ra1.z); as[sa+7]=f2tf(ra1.w);
        int sb = brow*BS_LD + bcol;
        bs[sb+0]=f2tf(rb0.x); bs[sb+1]=f2tf(rb0.y); bs[sb+2]=f2tf(rb0.z); bs[sb+3]=f2tf(rb0.w);
        bs[sb+4]=f2tf(rb1.x); bs[sb+5]=f2tf(rb1.y); bs[sb+6]=f2tf(rb1.z); bs[sb+7]=f2tf(rb1.w);
    }
    __syncthreads();

    for (int kt = 0; kt < KT; kt++) {
        int cur = kt & 1;
        if (kt + 1 < KT) {
            int k0 = (kt + 1) * 16;
            ra0 = *(const float4*)(Aptr + k0);
            ra1 = *(const float4*)(Aptr + k0 + 4);
            rb0 = *(const float4*)(Bptr + (size_t)k0*N);
            rb1 = *(const float4*)(Bptr + (size_t)k0*N + 4);
        }
        const float* as = As[cur];
        const float* bs = Bs[cur];
#pragma unroll
        for (int ks = 0; ks < 2; ks++) {
            int k = ks * 8;
            unsigned af[2][4];
#pragma unroll
            for (int mt = 0; mt < 2; mt++) {
                int r0 = (wm*32 + mt*16 + qr) * AS_LD + k + qc;
                af[mt][0] = __float_as_uint(as[r0]);
                af[mt][1] = __float_as_uint(as[r0 + 8*AS_LD]);
                af[mt][2] = __float_as_uint(as[r0 + 4]);
                af[mt][3] = __float_as_uint(as[r0 + 8*AS_LD + 4]);
            }
            unsigned bf[8][2];
#pragma unroll
            for (int nt = 0; nt < 8; nt++) {
                int c0 = (k + qc)*BS_LD + wn*64 + nt*8 + qr;
                bf[nt][0] = __float_as_uint(bs[c0]);
                bf[nt][1] = __float_as_uint(bs[c0 + 4*BS_LD]);
            }
#pragma unroll
            for (int mt = 0; mt < 2; mt++)
#pragma unroll
                for (int nt = 0; nt < 8; nt++)
                    mma_tf32(acc[mt][nt], af[mt], bf[nt]);
        }
        if (kt + 1 < KT) {
            float* asw = As[cur ^ 1]; float* bsw = Bs[cur ^ 1];
            int sa = arow*AS_LD + acol;
            asw[sa+0]=f2tf(ra0.x); asw[sa+1]=f2tf(ra0.y); asw[sa+2]=f2tf(ra0.z); asw[sa+3]=f2tf(ra0.w);
            asw[sa+4]=f2tf(ra1.x); asw[sa+5]=f2tf(ra1.y); asw[sa+6]=f2tf(ra1.z); asw[sa+7]=f2tf(ra1.w);
            int sb = brow*BS_LD + bcol;
            bsw[sb+0]=f2tf(rb0.x); bsw[sb+1]=f2tf(rb0.y); bsw[sb+2]=f2tf(rb0.z); bsw[sb+3]=f2tf(rb0.w);
            bsw[sb+4]=f2tf(rb1.x); bsw[sb+5]=f2tf(rb1.y); bsw[sb+6]=f2tf(rb1.z); bsw[sb+7]=f2tf(rb1.w);
        }
        __syncthreads();
    }

#pragma unroll
    for (int mt = 0; mt < 2; mt++) {
        int mA = m0 + wm*32 + mt*16 + qr;
        int mB = mA + 8;
#pragma unroll
        for (int nt = 0; nt < 8; nt++) {
            int n = n0 + wn*64 + nt*8 + qc*2;
            float b0 = bias[n], b1 = bias[n + 1];
            float v0 = acc[mt][nt][0] + b0;
            float v1 = acc[mt][nt][1] + b1;
            float v2 = acc[mt][nt][2] + b0;
            float v3 = acc[mt][nt][3] + b1;
            if (act) {
                v0 = fast_elu(v0);
                v1 = fast_elu(v1);
                v2 = fast_elu(v2);
                v3 = fast_elu(v3);
            }
            if (res) {
                const float* rA = res + (size_t)mA*N + n;
                const float* rB = res + (size_t)mB*N + n;
                v0 += rA[0]; v1 += rA[1];
                v2 += rB[0]; v3 += rB[1];
            }
            if (permute) {
                int pn0 = (n & 15)*192 + (n >> 4);
                int pn1 = ((n+1) & 15)*192 + ((n+1) >> 4);
                C[(size_t)mA*N + pn0] = v0;
                C[(size_t)mA*N + pn1] = v1;
                C[(size_t)mB*N + pn0] = v2;
                C[(size_t)mB*N + pn1] = v3;
            } else {
                float2 oA; oA.x = v0; oA.y = v1;
                float2 oB; oB.x = v2; oB.y = v3;
                *(float2*)(C + (size_t)mA*N + n) = oA;
                *(float2*)(C + (size_t)mB*N + n) = oB;
            }
        }
    }
}

// ---------------- e -> LN(shfl-fused) -> [E|G] projection via tf32 mma -------
__global__ void __launch_bounds__(256) eg_kernel(
    const float* __restrict__ e,
    const float* __restrict__ lng, const float* __restrict__ lnb,
    const float* __restrict__ WE, const float* __restrict__ bE,
    const float* __restrict__ WG, const float* __restrict__ bG)
{
    __shared__ float xs[64*68];
    __shared__ float Wc[64*36];
    __shared__ float ob[32*65];
    __shared__ float sg[64], sb[64], sbc[32];
    int t = threadIdx.x;
    size_t row0 = (size_t)blockIdx.x * 64;

    for (int i = t; i < 1024; i += 256) {
        int k = i >> 4, o = i & 15;
        Wc[k*36 + o]      = f2tf(WE[i]);
        Wc[k*36 + 16 + o] = f2tf(WG[i]);
    }
    if (t < 64) { sg[t] = lng[t]; sb[t] = lnb[t]; }
    if (t >= 64 && t < 80)  sbc[t - 64] = bE[t - 64];
    if (t >= 80 && t < 96)  sbc[t - 64] = bG[t - 80];
    __syncthreads();

#pragma unroll
    for (int i = 0; i < 4; i++) {
        int idx4 = t + i*256;
        int r = idx4 >> 4, c4 = idx4 & 15;
        float4 v = *(const float4*)&e[row0*64 + (size_t)r*64 + c4*4];
        float ps = v.x + v.y + v.z + v.w;
        float pq = v.x*v.x + v.y*v.y + v.z*v.z + v.w*v.w;
        ps += __shfl_xor_sync(0xffffffff, ps, 1);
        ps += __shfl_xor_sync(0xffffffff, ps, 2);
        ps += __shfl_xor_sync(0xffffffff, ps, 4);
        ps += __shfl_xor_sync(0xffffffff, ps, 8);
        pq += __shfl_xor_sync(0xffffffff, pq, 1);
        pq += __shfl_xor_sync(0xffffffff, pq, 2);
        pq += __shfl_xor_sync(0xffffffff, pq, 4);
        pq += __shfl_xor_sync(0xffffffff, pq, 8);
        float mu = ps * (1.0f/64.0f);
        float rs = rsqrtf(pq * (1.0f/64.0f) - mu*mu + 1e-5f);
        int c = c4*4;
        xs[r*68 + c + 0] = f2tf((v.x - mu)*rs*sg[c+0] + sb[c+0]);
        xs[r*68 + c + 1] = f2tf((v.y - mu)*rs*sg[c+1] + sb[c+1]);
        xs[r*68 + c + 2] = f2tf((v.z - mu)*rs*sg[c+2] + sb[c+2]);
        xs[r*68 + c + 3] = f2tf((v.w - mu)*rs*sg[c+3] + sb[c+3]);
    }
    __syncthreads();

    int lane = t & 31;
    int w = t >> 5;
    int wm = w & 3;
    int wn = w >> 2;
    int qr = lane >> 2, qc = lane & 3;
    {
        float acc[2][4];
#pragma unroll
        for (int j = 0; j < 2; j++)
#pragma unroll
            for (int k = 0; k < 4; k++) acc[j][k] = 0.f;
#pragma unroll
        for (int k8 = 0; k8 < 8; k8++) {
            int k = k8 * 8;
            unsigned af[4];
            int r0 = (wm*16 + qr)*68 + k + qc;
            af[0] = __float_as_uint(xs[r0]);
            af[1] = __float_as_uint(xs[r0 + 8*68]);
            af[2] = __float_as_uint(xs[r0 + 4]);
            af[3] = __float_as_uint(xs[r0 + 8*68 + 4]);
#pragma unroll
            for (int nt = 0; nt < 2; nt++) {
                int c0 = (k + qc)*36 + wn*16 + nt*8 + qr;
                unsigned bf[2];
                bf[0] = __float_as_uint(Wc[c0]);
                bf[1] = __float_as_uint(Wc[c0 + 4*36]);
                mma_tf32(acc[nt], af, bf);
            }
        }
#pragma unroll
        for (int nt = 0; nt < 2; nt++) {
            int o = wn*16 + nt*8 + qc*2;
            int lA = wm*16 + qr, lB = lA + 8;
            float v0 = acc[nt][0] + sbc[o];
            float v1 = acc[nt][1] + sbc[o+1];
            float v2 = acc[nt][2] + sbc[o];
            float v3 = acc[nt][3] + sbc[o+1];
            if (o >= 16) {
                v0 = fast_sigmoid(v0);
                v1 = fast_sigmoid(v1);
                v2 = fast_sigmoid(v2);
                v3 = fast_sigmoid(v3);
            }
            ob[o*65 + lA]     = v0;
            ob[(o+1)*65 + lA] = v1;
            ob[o*65 + lB]     = v2;
            ob[(o+1)*65 + lB] = v3;
        }
    }
    __syncthreads();

    int b_ = (int)(row0 >> 18);
    int rem = (int)(row0 & (NN - 1));
    int l = rem >> 9, m0 = rem & 511;
#pragma unroll
    for (int i = 0; i < 8; i++) {
        int idx = t + i*256;
        int o = idx >> 6, rr = idx & 63;
        float val = ob[o*65 + rr];
        int hd = o & 15;
        size_t dst = ((size_t)(b_*HEADS + hd))*NN + (size_t)l*512 + m0 + rr;
        if (o < 16) g_E[dst] = val; else g_gate[dst] = val;
    }
}

// ---------------- fused attention v10 (tf32 mma, 512 threads, 2 blocks/SM) ---
#define AV3_HLD  37
#define AV3_HS   0
#define AV3_QS   18944
#define AV3_KVS  21120
#define AV3_SMEM 25504
__global__ void __launch_bounds__(512) av2_kernel(const float* __restrict__ qkv)
{
    extern __shared__ float sm[];
    float* Hs  = sm + AV3_HS;
    float* Qs  = sm + AV3_QS;
    float* KVs = sm + AV3_KVS;

    int t = threadIdx.x;
    int l0 = blockIdx.x * 32;
    int z = blockIdx.y;
    int b = z >> 4, hd = z & 15;
    int lane = t & 31;
    int w = t >> 5;               // 0..15
    int wm = w & 1;               // l-tile of 16
    int wn = w >> 1;              // m/n chunk of 8 (0..7)
    int qr = lane >> 2, qc = lane & 3;
    size_t zbase = (size_t)z * NN;
    const float* qb = qkv + (size_t)b*NSEQ*3*NDIM + hd*192;

    // load Q strip [l][d] coalesced (512 float4s, 1 per thread)
    {
        int lloc = t >> 4, d4 = t & 15;
        float4 v = *(const float4*)&qb[(size_t)(l0 + lloc)*(3*NDIM) + d4*4];
        v.x = f2tf(v.x); v.y = f2tf(v.y); v.z = f2tf(v.z); v.w = f2tf(v.w);
        *(float4*)&Qs[lloc*68 + d4*4] = v;
    }

    // Phase 1 with K-tile register prefetch
    float4 pk[2];
#pragma unroll
    for (int i = 0; i < 2; i++) {
        int idx4 = t + i*512;
        int mloc = idx4 >> 4, d4 = idx4 & 15;
        pk[i] = *(const float4*)&qb[(size_t)mloc*(3*NDIM) + 64 + d4*4];
    }
    for (int mt = 0; mt < 8; mt++) {
        int m0g = mt * 64;
#pragma unroll
        for (int i = 0; i < 2; i++) {
            int idx4 = t + i*512;
            int mloc = idx4 >> 4, d4 = idx4 & 15;
            KVs[(d4*4+0)*68 + mloc] = f2tf(pk[i].x);
            KVs[(d4*4+1)*68 + mloc] = f2tf(pk[i].y);
            KVs[(d4*4+2)*68 + mloc] = f2tf(pk[i].z);
            KVs[(d4*4+3)*68 + mloc] = f2tf(pk[i].w);
        }
        __syncthreads();
        if (mt < 7) {
            int m1 = (mt + 1) * 64;
#pragma unroll
            for (int i = 0; i < 2; i++) {
                int idx4 = t + i*512;
                int mloc = idx4 >> 4, d4 = idx4 & 15;
                pk[i] = *(const float4*)&qb[(size_t)(m1 + mloc)*(3*NDIM) + 64 + d4*4];
            }
        }

        float acc[4];
#pragma unroll
        for (int k = 0; k < 4; k++) acc[k] = 0.f;
#pragma unroll
        for (int k8 = 0; k8 < 8; k8++) {
            int k = k8 * 8;
            unsigned af[4];
            int r0 = (wm*16 + qr)*68 + k + qc;
            af[0] = __float_as_uint(Qs[r0]);
            af[1] = __float_as_uint(Qs[r0 + 8*68]);
            af[2] = __float_as_uint(Qs[r0 + 4]);
            af[3] = __float_as_uint(Qs[r0 + 8*68 + 4]);
            int c0 = (k + qc)*68 + wn*8 + qr;
            unsigned bf[2];
            bf[0] = __float_as_uint(KVs[c0]);
            bf[1] = __float_as_uint(KVs[c0 + 4*68]);
            mma_tf32(acc, af, bf);
        }
        {
            int mg = m0g + wn*8 + qc*2;
            int lA = wm*16 + qr, lB = lA + 8;
            Hs[(mg+0)*AV3_HLD + lA] = acc[0];
            Hs[(mg+1)*AV3_HLD + lA] = acc[1];
            Hs[(mg+0)*AV3_HLD + lB] = acc[2];
            Hs[(mg+1)*AV3_HLD + lB] = acc[3];
        }
        __syncthreads();
    }

    // scale, clip, +E -> g_H and Hs (coalesced, 32 iters)
    for (int ii = 0; ii < 32; ii++) {
        int idx = ii*512 + t;
        int l = idx >> 9, m = idx & 511;
        size_t ro = zbase + (size_t)(l0 + l)*512 + m;
        float v = fminf(fmaxf(Hs[m*AV3_HLD + l]*0.125f, -5.f), 5.f) + g_E[ro];
        g_H[ro] = v;
        Hs[m*AV3_HLD + l] = v;
    }
    __syncthreads();

    // fused softmax + gate + inv (16 threads/row)
    {
        int r = t >> 4, part = t & 15;
        const float* gr = g_gate + zbase + (size_t)(l0 + r)*512;
        float mx = -1e30f;
        for (int i = 0; i < 32; i++) {
            int m = i*16 + part;
            mx = fmaxf(mx, Hs[m*AV3_HLD + r]);
        }
        mx = fmaxf(mx, __shfl_xor_sync(0xffffffff, mx, 1));
        mx = fmaxf(mx, __shfl_xor_sync(0xffffffff, mx, 2));
        mx = fmaxf(mx, __shfl_xor_sync(0xffffffff, mx, 4));
        mx = fmaxf(mx, __shfl_xor_sync(0xffffffff, mx, 8));
        float s = 0.f;
        for (int i = 0; i < 32; i++) {
            int m = i*16 + part;
            float ve = __expf(Hs[m*AV3_HLD + r] - mx);
            s += ve;
            Hs[m*AV3_HLD + r] = ve * gr[m];
        }
        s += __shfl_xor_sync(0xffffffff, s, 1);
        s += __shfl_xor_sync(0xffffffff, s, 2);
        s += __shfl_xor_sync(0xffffffff, s, 4);
        s += __shfl_xor_sync(0xffffffff, s, 8);
        float inv = 1.0f / s;
        for (int i = 0; i < 32; i++) {
            int m = i*16 + part;
            Hs[m*AV3_HLD + r] = f2tf(Hs[m*AV3_HLD + r] * inv);
        }
    }
    __syncthreads();

    // Phase 4: A@V with V-tile register prefetch
    float acc2[4];
#pragma unroll
    for (int k = 0; k < 4; k++) acc2[k] = 0.f;
    float4 pv[2];
#pragma unroll
    for (int i = 0; i < 2; i++) {
        int idx4 = t + i*512;
        int mloc = idx4 >> 4, k4 = idx4 & 15;
        pv[i] = *(const float4*)&qb[(size_t)mloc*(3*NDIM) + 128 + k4*4];
    }
    for (int mt = 0; mt < 8; mt++) {
        int m0g = mt * 64;
#pragma unroll
        for (int i = 0; i < 2; i++) {
            int idx4 = t + i*512;
            int mloc = idx4 >> 4, k4 = idx4 & 15;
            float4 v = pv[i];
            v.x = f2tf(v.x); v.y = f2tf(v.y); v.z = f2tf(v.z); v.w = f2tf(v.w);
            *(float4*)&KVs[mloc*68 + k4*4] = v;
        }
        __syncthreads();
        if (mt < 7) {
            int m1 = (mt + 1) * 64;
#pragma unroll
            for (int i = 0; i < 2; i++) {
                int idx4 = t + i*512;
                int mloc = idx4 >> 4, k4 = idx4 & 15;
                pv[i] = *(const float4*)&qb[(size_t)(m1 + mloc)*(3*NDIM) + 128 + k4*4];
            }
        }
#pragma unroll
        for (int k8 = 0; k8 < 8; k8++) {
            int kk = k8 * 8;
            unsigned af[4];
            int a0 = (m0g + kk + qc)*AV3_HLD + wm*16 + qr;
            af[0] = __float_as_uint(Hs[a0]);
            af[1] = __float_as_uint(Hs[a0 + 8]);
            af[2] = __float_as_uint(Hs[a0 + 4*AV3_HLD]);
            af[3] = __float_as_uint(Hs[a0 + 4*AV3_HLD + 8]);
            int c0 = (kk + qc)*68 + wn*8 + qr;
            unsigned bf[2];
            bf[0] = __float_as_uint(KVs[c0]);
            bf[1] = __float_as_uint(KVs[c0 + 4*68]);
            mma_tf32(acc2, af, bf);
        }
        __syncthreads();
    }
    {
        int lA = l0 + wm*16 + qr;
        int lB = lA + 8;
        int kout = wn*8 + qc*2;
        g_vatt[(size_t)(b*NSEQ + lA)*NDIM + (kout+0)*16 + hd] = acc2[0];
        g_vatt[(size_t)(b*NSEQ + lA)*NDIM + (kout+1)*16 + hd] = acc2[1];
        g_vatt[(size_t)(b*NSEQ + lB)*NDIM + (kout+0)*16 + hd] = acc2[2];
        g_vatt[(size_t)(b*NSEQ + lB)*NDIM + (kout+1)*16 + hd] = acc2[3];
    }
}

// ---------------- persistent fused e-out (R15 256-thread config) ------------
#define EO_W1   0
#define EO_W2   8448
#define EO_WOE  17152
#define EO_HG   18176
#define EO_XS   18752
#define EO_XSN  20832
#define EO_HS   23008
#define EO_PAR  27232
#define EO_SMEM_FLOATS 27680
__global__ void __launch_bounds__(256) eout_kernel(
    const float* __restrict__ e,
    const float* __restrict__ WOe, const float* __restrict__ bOe,
    const float* __restrict__ lng, const float* __restrict__ lnb,
    const float* __restrict__ W1, const float* __restrict__ b1,
    const float* __restrict__ W2, const float* __restrict__ b2,
    float* __restrict__ eout)
{
    extern __shared__ float sm[];
    float* W1s  = sm + EO_W1;
    float* W2s  = sm + EO_W2;
    float* WOes = sm + EO_WOE;
    float* Hg   = sm + EO_HG;
    float* xs   = sm + EO_XS;
    float* xsn  = sm + EO_XSN;
    float* hs   = sm + EO_HS;
    float* sbOe = sm + EO_PAR;
    float* sge  = sbOe + 64;
    float* sbe  = sge  + 64;
    float* sb1  = sbe  + 64;
    float* sb2  = sb1  + 128;

    int t = threadIdx.x;
    int bid = blockIdx.x;
    int b_ = bid >> 9;
    int l  = bid & 511;
    const float* Hbase = g_H + (size_t)(b_*HEADS)*NN + (size_t)l*512;

    for (int i = t; i < 8192; i += 256) {
        W1s[(i >> 7)*132 + (i & 127)] = f2tf(W1[i]);
        W2s[(i >> 6)*68  + (i & 63)]  = f2tf(W2[i]);
    }
    for (int i = t; i < 1024; i += 256) WOes[i] = WOe[i];
    if (t < 64) { sbOe[t] = bOe[t]; sge[t] = lng[t]; sbe[t] = lnb[t]; sb2[t] = b2[t]; }
    if (t >= 64 && t < 192) sb1[t - 64] = b1[t - 64];

    int lane = t & 31;
    int w = t >> 5;
    int wm = w & 1;
    int wn = w >> 1;
    int qr = lane >> 2, qc = lane & 3;
    int tx = t & 15, ty = t >> 4;

    // prefetch group 0
    float hgp[2];
    float4 ep[2];
    {
        int hd0 = t >> 5, m0_ = t & 31;
        hgp[0] = Hbase[(size_t)hd0*NN + m0_];
        hgp[1] = Hbase[(size_t)(hd0 + 8)*NN + m0_];
        size_t row0 = (size_t)bid * 512;
#pragma unroll
        for (int i = 0; i < 2; i++)
            ep[i] = *(const float4*)&e[(row0 + ty*2 + i)*64 + tx*4];
    }
    __syncthreads();

    for (int g = 0; g < 16; g++) {
        int m0 = g * 32;
        size_t row0 = (size_t)bid * 512 + m0;

        {
            int hd0 = t >> 5, m = t & 31;
            Hg[hd0*36 + m]       = hgp[0];
            Hg[(hd0 + 8)*36 + m] = hgp[1];
        }
        __syncthreads();

        // Phase A (fused): x = Hg^T@WOe + bOe + e; LN via shfl; xsn = tf32(LN(x))
        {
            float acc[2][4];
#pragma unroll
            for (int i = 0; i < 2; i++)
#pragma unroll
                for (int j = 0; j < 4; j++) acc[i][j] = 0.f;
#pragma unroll
            for (int hd = 0; hd < 16; hd++) {
                float a[2], wv[4];
#pragma unroll
                for (int i = 0; i < 2; i++) a[i] = Hg[hd*36 + ty*2 + i];
#pragma unroll
                for (int j = 0; j < 4; j++) wv[j] = WOes[hd*64 + tx*4 + j];
#pragma unroll
                for (int i = 0; i < 2; i++)
#pragma unroll
                    for (int j = 0; j < 4; j++) acc[i][j] += a[i]*wv[j];
            }
#pragma unroll
            for (int i = 0; i < 2; i++) {
                int r = ty*2 + i;
                float4 ev = ep[i];
                float v0 = acc[i][0] + sbOe[tx*4+0] + ev.x;
                float v1 = acc[i][1] + sbOe[tx*4+1] + ev.y;
                float v2 = acc[i][2] + sbOe[tx*4+2] + ev.z;
                float v3 = acc[i][3] + sbOe[tx*4+3] + ev.w;
                xs[r*65 + tx*4 + 0] = v0;
                xs[r*65 + tx*4 + 1] = v1;
                xs[r*65 + tx*4 + 2] = v2;
                xs[r*65 + tx*4 + 3] = v3;
                float ps = v0 + v1 + v2 + v3;
                float pq = v0*v0 + v1*v1 + v2*v2 + v3*v3;
                ps += __shfl_xor_sync(0xffffffff, ps, 1);
                ps += __shfl_xor_sync(0xffffffff, ps, 2);
                ps += __shfl_xor_sync(0xffffffff, ps, 4);
                ps += __shfl_xor_sync(0xffffffff, ps, 8);
                pq += __shfl_xor_sync(0xffffffff, pq, 1);
                pq += __shfl_xor_sync(0xffffffff, pq, 2);
                pq += __shfl_xor_sync(0xffffffff, pq, 4);
                pq += __shfl_xor_sync(0xffffffff, pq, 8);
                float mu = ps * (1.0f/64.0f);
                float rs = rsqrtf(pq * (1.0f/64.0f) - mu*mu + 1e-5f);
                int c = tx*4;
                xsn[r*68 + c + 0] = f2tf((v0 - mu)*rs*sge[c+0] + sbe[c+0]);
                xsn[r*68 + c + 1] = f2tf((v1 - mu)*rs*sge[c+1] + sbe[c+1]);
                xsn[r*68 + c + 2] = f2tf((v2 - mu)*rs*sge[c+2] + sbe[c+2]);
                xsn[r*68 + c + 3] = f2tf((v3 - mu)*rs*sge[c+3] + sbe[c+3]);
            }
        }
        __syncthreads();

        // prefetch next group's Hg + e (overlaps C/E mma phases)
        if (g < 15) {
            int m1 = (g + 1) * 32;
            int hd0 = t >> 5, mm = t & 31;
            hgp[0] = Hbase[(size_t)hd0*NN + m1 + mm];
            hgp[1] = Hbase[(size_t)(hd0 + 8)*NN + m1 + mm];
            size_t row1 = (size_t)bid * 512 + m1;
#pragma unroll
            for (int i = 0; i < 2; i++)
                ep[i] = *(const float4*)&e[(row1 + ty*2 + i)*64 + tx*4];
        }

        // Phase C (mma): hidden = elu( xsn @ W1 + b1 )
        {
            float acc[4][4];
#pragma unroll
            for (int j = 0; j < 4; j++)
#pragma unroll
                for (int k = 0; k < 4; k++) acc[j][k] = 0.f;
#pragma unroll
            for (int k8 = 0; k8 < 8; k8++) {
                int k = k8 * 8;
                unsigned af[4];
                int r0 = (wm*16 + qr)*68 + k + qc;
                af[0] = __float_as_uint(xsn[r0]);
                af[1] = __float_as_uint(xsn[r0 + 8*68]);
                af[2] = __float_as_uint(xsn[r0 + 4]);
                af[3] = __float_as_uint(xsn[r0 + 8*68 + 4]);
#pragma unroll
                for (int nt = 0; nt < 4; nt++) {
                    int c0 = (k + qc)*132 + wn*32 + nt*8 + qr;
                    unsigned bf[2];
                    bf[0] = __float_as_uint(W1s[c0]);
                    bf[1] = __float_as_uint(W1s[c0 + 4*132]);
                    mma_tf32(acc[nt], af, bf);
                }
            }
#pragma unroll
            for (int nt = 0; nt < 4; nt++) {
                int n = wn*32 + nt*8 + qc*2;
                int mA = wm*16 + qr, mB = mA + 8;
                float v0 = fast_elu(acc[nt][0] + sb1[n]);
                float v1 = fast_elu(acc[nt][1] + sb1[n+1]);
                float v2 = fast_elu(acc[nt][2] + sb1[n]);
                float v3 = fast_elu(acc[nt][3] + sb1[n+1]);
                hs[mA*132 + n]     = f2tf(v0);
                hs[mA*132 + n + 1] = f2tf(v1);
                hs[mB*132 + n]     = f2tf(v2);
                hs[mB*132 + n + 1] = f2tf(v3);
            }
        }
        __syncthreads();

        // Phase E (mma): out = hs @ W2 + b2 + xs
        {
            float acc[2][4];
#pragma unroll
            for (int j = 0; j < 2; j++)
#pragma unroll
                for (int k = 0; k < 4; k++) acc[j][k] = 0.f;
#pragma unroll
            for (int k8 = 0; k8 < 16; k8++) {
                int k = k8 * 8;
                unsigned af[4];
                int r0 = (wm*16 + qr)*132 + k + qc;
                af[0] = __float_as_uint(hs[r0]);
                af[1] = __float_as_uint(hs[r0 + 8*132]);
                af[2] = __float_as_uint(hs[r0 + 4]);
                af[3] = __float_as_uint(hs[r0 + 8*132 + 4]);
#pragma unroll
                for (int nt = 0; nt < 2; nt++) {
                    int c0 = (k + qc)*68 + wn*16 + nt*8 + qr;
                    unsigned bf[2];
                    bf[0] = __float_as_uint(W2s[c0]);
                    bf[1] = __float_as_uint(W2s[c0 + 4*68]);
                    mma_tf32(acc[nt], af, bf);
                }
            }
#pragma unroll
            for (int nt = 0; nt < 2; nt++) {
                int n = wn*16 + nt*8 + qc*2;
                int mA = wm*16 + qr, mB = mA + 8;
                float2 oA, oB;
                oA.x = acc[nt][0] + sb2[n]   + xs[mA*65 + n];
                oA.y = acc[nt][1] + sb2[n+1] + xs[mA*65 + n + 1];
                oB.x = acc[nt][2] + sb2[n]   + xs[mB*65 + n];
                oB.y = acc[nt][3] + sb2[n+1] + xs[mB*65 + n + 1];
                *(float2*)&eout[(row0 + mA)*64 + n] = oA;
                *(float2*)&eout[(row0 + mB)*64 + n] = oB;
            }
        }
        __syncthreads();
    }
}

// ---------------- host launcher ----------------
extern "C" void kernel_launch(void* const* d_in, const int* in_sizes, int n_in,
                              void* d_out, int out_size)
{
    const float* h        = (const float*)d_in[0];
    const float* e        = (const float*)d_in[1];
    const float* ln_h_g   = (const float*)d_in[2];
    const float* ln_h_b   = (const float*)d_in[3];
    const float* ln_e_g   = (const float*)d_in[4];
    const float* ln_e_b   = (const float*)d_in[5];
    const float* W_E      = (const float*)d_in[6];
    const float* b_E      = (const float*)d_in[7];
    const float* W_QKV    = (const float*)d_in[8];
    const float* b_QKV    = (const float*)d_in[9];
    const float* W_G      = (const float*)d_in[10];
    const float* b_G      = (const float*)d_in[11];
    const float* W_Oh     = (const float*)d_in[12];
    const float* b_Oh     = (const float*)d_in[13];
    const float* ffn_ln_h_g = (const float*)d_in[14];
    const float* ffn_ln_h_b = (const float*)d_in[15];
    const float* W_h1     = (const float*)d_in[16];
    const float* b_h1     = (const float*)d_in[17];
    const float* W_h2     = (const float*)d_in[18];
    const float* b_h2     = (const float*)d_in[19];
    const float* W_Oe     = (const float*)d_in[20];
    const float* b_Oe     = (const float*)d_in[21];
    const float* ffn_ln_e_g = (const float*)d_in[22];
    const float* ffn_ln_e_b = (const float*)d_in[23];
    const float* W_e1     = (const float*)d_in[24];
    const float* b_e1     = (const float*)d_in[25];
    const float* W_e2     = (const float*)d_in[26];
    const float* b_e2     = (const float*)d_in[27];

    float* out_h = (float*)d_out;
    float* out_e = out_h + H_OUT_ELEMS;

    float *p_hln, *p_qkv, *p_vatt, *p_h1, *p_h2, *p_act;
    cudaGetSymbolAddress((void**)&p_hln,  g_hln);
    cudaGetSymbolAddress((void**)&p_qkv,  g_qkv);
    cudaGetSymbolAddress((void**)&p_vatt, g_vatt);
    cudaGetSymbolAddress((void**)&p_h1,   g_h1);
    cudaGetSymbolAddress((void**)&p_h2,   g_h2);
    cudaGetSymbolAddress((void**)&p_act,  g_act);

    // h path pre-attention (QKV gemm writes head-major permuted output)
    ln1024_kernel<<<BN, 256>>>(h, ln_h_g, ln_h_b, p_hln);
    gemm_tc_kernel<<<dim3(3*NDIM/128, BN/128), 256>>>(p_hln, W_QKV, b_QKV, nullptr, p_qkv,
                                                      BN, 3*NDIM, NDIM, 0, 1);
    // e path: LN + E/G projections (mma, fused LN)
    eg_kernel<<<(unsigned)(EROWS/64), 256>>>(e, ln_e_g, ln_e_b, W_E, b_E, W_G, b_G);
    // fused attention (tf32 mma, 512 threads, 2 blocks/SM)
    cudaFuncSetAttribute(av2_kernel, cudaFuncAttributeMaxDynamicSharedMemorySize,
                         AV3_SMEM * 4);
    av2_kernel<<<dim3(16, BHN), 512, AV3_SMEM * 4>>>(p_qkv);
    // h path post-attention
    gemm_tc_kernel<<<dim3(NDIM/128, BN/128), 256>>>(p_vatt, W_Oh, b_Oh, h, p_h1,
                                                    BN, NDIM, NDIM, 0, 0);
    ln1024_kernel<<<BN, 256>>>(p_h1, ffn_ln_h_g, ffn_ln_h_b, p_h2);
    gemm_tc_kernel<<<dim3(FFN_H/128, BN/128), 256>>>(p_h2, W_h1, b_h1, nullptr, p_act,
                                                     BN, FFN_H, NDIM, 1, 0);
    gemm_tc_kernel<<<dim3(NDIM/128, BN/128), 256>>>(p_act, W_h2, b_h2, p_h1, out_h,
                                                    BN, NDIM, FFN_H, 0, 0);
    // fused e output path (256 threads, R15 config)
    cudaFuncSetAttribute(eout_kernel, cudaFuncAttributeMaxDynamicSharedMemorySize,
                         EO_SMEM_FLOATS * 4);
    eout_kernel<<<BN, 256, EO_SMEM_FLOATS * 4>>>(
        e, W_Oe, b_Oe, ffn_ln_e_g, ffn_ln_e_b, W_e1, b_e1, W_e2, b_e2, out_e);
}